// round 1
// baseline (speedup 1.0000x reference)
#include <cuda_runtime.h>
#include <stdint.h>

#define NUM_BINS 256
#define NCH_SAMPLE 3
#define NCH_TOTAL 6

// Scratch (no allocations allowed in kernel_launch).
__device__ int   g_hist[NCH_SAMPLE][NUM_BINS];
__device__ float g_lut[NCH_SAMPLE][NUM_BINS];

__global__ void zero_hist_kernel() {
    int i = blockIdx.x * blockDim.x + threadIdx.x;
    if (i < NCH_SAMPLE * NUM_BINS) ((int*)g_hist)[i] = 0;
}

// Grid: (blocksX, 3). Each block builds a 4-way replicated smem histogram
// for channel blockIdx.y, then flushes once to the global per-channel bins.
__global__ void hist_kernel(const float* __restrict__ img, int npx) {
    __shared__ int sh[4][NUM_BINS];
    const int c = blockIdx.y;
    const int t = threadIdx.x;

    for (int i = t; i < 4 * NUM_BINS; i += blockDim.x) ((int*)sh)[i] = 0;
    __syncthreads();

    const float4* p = (const float4*)(img + (size_t)c * npx);
    const int n4 = npx >> 2;
    const int sub = t & 3;
    const int stride = gridDim.x * blockDim.x;

    for (int i = blockIdx.x * blockDim.x + t; i < n4; i += stride) {
        float4 v = p[i];
        int bx = min(NUM_BINS - 1, max(0, (int)v.x));
        int by = min(NUM_BINS - 1, max(0, (int)v.y));
        int bz = min(NUM_BINS - 1, max(0, (int)v.z));
        int bw = min(NUM_BINS - 1, max(0, (int)v.w));
        atomicAdd(&sh[sub][bx], 1);
        atomicAdd(&sh[sub][by], 1);
        atomicAdd(&sh[sub][bz], 1);
        atomicAdd(&sh[sub][bw], 1);
    }
    __syncthreads();

    for (int i = t; i < NUM_BINS; i += blockDim.x) {
        int s = sh[0][i] + sh[1][i] + sh[2][i] + sh[3][i];
        if (s) atomicAdd(&g_hist[c][i], s);
    }
}

// One 256-thread block per channel. Computes the torchvision/JAX LUT exactly:
//   last_nz = last index with hist>0
//   step    = (total - hist[last_nz]) // 255
//   cum     = inclusive cumsum(hist)
//   lut[0]  = 0 ; lut[i] = clip((cum[i-1] + step//2) // step, 0, 255)
//   step==0 -> identity mapping (where(step==0, chan, lut[chan]))
__global__ void lut_kernel() {
    const int c = blockIdx.x;
    const int t = threadIdx.x;
    __shared__ int hist[NUM_BINS];
    __shared__ int cum[NUM_BINS];
    __shared__ int s_lastnz;

    int h = g_hist[c][t];
    hist[t] = h;
    cum[t] = h;
    if (t == 0) s_lastnz = 0;
    __syncthreads();

    // Hillis-Steele inclusive scan
    #pragma unroll
    for (int off = 1; off < NUM_BINS; off <<= 1) {
        int tmp = (t >= off) ? cum[t - off] : 0;
        __syncthreads();
        cum[t] += tmp;
        __syncthreads();
    }

    if (h > 0) atomicMax(&s_lastnz, t);
    __syncthreads();

    const int total = cum[NUM_BINS - 1];
    const int last  = s_lastnz;
    const int step  = (total - hist[last]) / (NUM_BINS - 1);

    float out;
    if (step == 0) {
        out = (float)t;   // identity: where(step==0, chan, ...)
    } else {
        int l = (t == 0) ? 0 : (cum[t - 1] + (step >> 1)) / step;
        l = min(NUM_BINS - 1, max(0, l));
        out = (float)l;
    }
    g_lut[c][t] = out;
}

// Grid: (blocksX, 6). Channels 0..2 -> LUT remap via smem LUT;
// channels 3..5 -> straight copy. float4 throughout.
__global__ void apply_kernel(const float* __restrict__ img,
                             float* __restrict__ out, int npx) {
    const int c = blockIdx.y;
    __shared__ float lut[NUM_BINS];

    const bool remap = (c < NCH_SAMPLE);
    if (remap) {
        for (int i = threadIdx.x; i < NUM_BINS; i += blockDim.x)
            lut[i] = g_lut[c][i];
        __syncthreads();
    }

    const float4* p = (const float4*)(img + (size_t)c * npx);
    float4*       q = (float4*)(out + (size_t)c * npx);
    const int n4 = npx >> 2;
    const int stride = gridDim.x * blockDim.x;

    if (remap) {
        for (int i = blockIdx.x * blockDim.x + threadIdx.x; i < n4; i += stride) {
            float4 v = p[i];
            float4 r;
            r.x = lut[min(NUM_BINS - 1, max(0, (int)v.x))];
            r.y = lut[min(NUM_BINS - 1, max(0, (int)v.y))];
            r.z = lut[min(NUM_BINS - 1, max(0, (int)v.z))];
            r.w = lut[min(NUM_BINS - 1, max(0, (int)v.w))];
            q[i] = r;
        }
    } else {
        for (int i = blockIdx.x * blockDim.x + threadIdx.x; i < n4; i += stride) {
            q[i] = p[i];
        }
    }
}

extern "C" void kernel_launch(void* const* d_in, const int* in_sizes, int n_in,
                              void* d_out, int out_size) {
    const float* img = (const float*)d_in[0];
    float* out = (float*)d_out;
    const int npx = in_sizes[0] / NCH_TOTAL;   // 2048*4096 = 8388608

    zero_hist_kernel<<<3, 256>>>();
    hist_kernel<<<dim3(256, NCH_SAMPLE), 256>>>(img, npx);
    lut_kernel<<<NCH_SAMPLE, 256>>>();
    apply_kernel<<<dim3(2048, NCH_TOTAL), 256>>>(img, out, npx);
}